// round 2
// baseline (speedup 1.0000x reference)
#include <cuda_runtime.h>
#include <cstddef>

// ---------------------------------------------------------------------------
// HyperNodeAggregation: out = bmm(V, softmax(Q Kᵀ)ᵀ) with 1x1-conv Q/K/V.
// Restructured: E_b = Wq (Wk G_b)ᵀ + u1 bkᵀ + bq u2ᵀ,  G_b = X_b X_bᵀ.
// All fp32. Stages: rowsum -> gemv(u1,u2) -> G (split-K) -> reduce -> K̂ -> V
//                   -> E (rank-2 epilogue) -> softmax -> out.
// ---------------------------------------------------------------------------

#define BM 128
#define BN 128
#define BKD 16
#define TM 8
#define TN 8
#define NTHREADS 256

// Scratch (device globals: allocation-free rule)
__device__ float g_s   [4 * 512];
__device__ float g_u1  [4 * 4096];
__device__ float g_u2  [4 * 4096];
__device__ float g_Gp  [4 * 8 * 512 * 512];   // split-K partials, 32 MB
__device__ float g_G   [4 * 512 * 512];       // 4 MB
__device__ float g_Khat[4 * 4096 * 512];      // 32 MB
__device__ float g_v   [4 * 512 * 4096];      // 32 MB
__device__ float g_E   [67108864];            // 4*4096*4096, 256 MB

// ---------------------------------------------------------------------------
// Tiled SGEMM: C = A * op(B), A row-major [M,K] (lda), op(B)=B [K,N] (ldb) if
// !BT, else Bᵀ with B row-major [N,K] (ldb). Batched over grid.z with strides;
// optional split-K decomposition (nsplit>1) writing per-split partials.
// MODE 0: none; MODE 1: +e0[m]; MODE 2: +e0[m]*e1[n] + e2[m]*e3[n].
// All dims assumed multiples of tile sizes (true here: 512/4096).
// ---------------------------------------------------------------------------
template<int MODE, bool BT>
__global__ __launch_bounds__(NTHREADS)
void sgemm_kernel(const float* __restrict__ A, const float* __restrict__ B,
                  float* __restrict__ C,
                  int M, int N, int K, int lda, int ldb, int ldc,
                  long long sA, long long sB, long long sC,
                  int nsplit, int spA, int spB, long long spC,
                  const float* __restrict__ e0, long long se0,
                  const float* __restrict__ e1, long long se1,
                  const float* __restrict__ e2, long long se2,
                  const float* __restrict__ e3, long long se3)
{
    __shared__ __align__(16) float As[BKD][BM];
    __shared__ __align__(16) float Bs[BKD][BN];

    const int z   = blockIdx.z;
    const int bat = z / nsplit;
    const int sp  = z - bat * nsplit;

    const float* Ab = A + (long long)bat * sA + (long long)sp * spA
                        + (size_t)blockIdx.y * BM * lda;
    const float* Bb = B + (long long)bat * sB + (long long)sp * spB
                        + (BT ? (size_t)blockIdx.x * BN * ldb
                              : (size_t)blockIdx.x * BN);
    float* Cb = C + (long long)bat * sC + (long long)sp * spC;

    const int tid = threadIdx.x;
    const int tx  = tid & 15;   // N dir
    const int ty  = tid >> 4;   // M dir

    float acc[TM][TN];
    #pragma unroll
    for (int i = 0; i < TM; i++)
        #pragma unroll
        for (int j = 0; j < TN; j++) acc[i][j] = 0.f;

    for (int k0 = 0; k0 < K; k0 += BKD) {
        // A tile: 128 rows x 16 cols -> transposed into As[k][m]
        #pragma unroll
        for (int i = 0; i < 2; i++) {
            int idx = tid + i * NTHREADS;     // 0..511
            int row = idx >> 2;               // 0..127
            int c4  = (idx & 3) << 2;         // 0,4,8,12
            const float4 va = *reinterpret_cast<const float4*>(
                Ab + (size_t)row * lda + (k0 + c4));
            As[c4 + 0][row] = va.x;
            As[c4 + 1][row] = va.y;
            As[c4 + 2][row] = va.z;
            As[c4 + 3][row] = va.w;
        }
        if (BT) {
            #pragma unroll
            for (int i = 0; i < 2; i++) {
                int idx = tid + i * NTHREADS;
                int row = idx >> 2;           // n within tile
                int c4  = (idx & 3) << 2;
                const float4 vb = *reinterpret_cast<const float4*>(
                    Bb + (size_t)row * ldb + (k0 + c4));
                Bs[c4 + 0][row] = vb.x;
                Bs[c4 + 1][row] = vb.y;
                Bs[c4 + 2][row] = vb.z;
                Bs[c4 + 3][row] = vb.w;
            }
        } else {
            #pragma unroll
            for (int i = 0; i < 2; i++) {
                int idx = tid + i * NTHREADS;
                int row = idx >> 5;           // 0..15 (k within tile)
                int c4  = (idx & 31) << 2;    // 0..124
                *reinterpret_cast<float4*>(&Bs[row][c4]) =
                    *reinterpret_cast<const float4*>(
                        Bb + (size_t)(k0 + row) * ldb + c4);
            }
        }
        __syncthreads();

        #pragma unroll
        for (int kk = 0; kk < BKD; kk++) {
            const float4 a0 = *reinterpret_cast<const float4*>(&As[kk][ty * TM]);
            const float4 a1 = *reinterpret_cast<const float4*>(&As[kk][ty * TM + 4]);
            const float4 b0 = *reinterpret_cast<const float4*>(&Bs[kk][tx * TN]);
            const float4 b1 = *reinterpret_cast<const float4*>(&Bs[kk][tx * TN + 4]);
            const float a[TM] = {a0.x, a0.y, a0.z, a0.w, a1.x, a1.y, a1.z, a1.w};
            const float b[TN] = {b0.x, b0.y, b0.z, b0.w, b1.x, b1.y, b1.z, b1.w};
            #pragma unroll
            for (int i = 0; i < TM; i++)
                #pragma unroll
                for (int j = 0; j < TN; j++)
                    acc[i][j] = fmaf(a[i], b[j], acc[i][j]);
        }
        __syncthreads();
    }

    const float* e0b = (MODE >= 1) ? (e0 + (long long)bat * se0) : nullptr;
    const float* e1b = (MODE == 2) ? (e1 + (long long)bat * se1) : nullptr;
    const float* e2b = (MODE == 2) ? (e2 + (long long)bat * se2) : nullptr;
    const float* e3b = (MODE == 2) ? (e3 + (long long)bat * se3) : nullptr;

    const int n0 = blockIdx.x * BN + tx * TN;
    #pragma unroll
    for (int i = 0; i < TM; i++) {
        const int m = blockIdx.y * BM + ty * TM + i;
        float c0 = 0.f, c1 = 0.f;
        if (MODE == 1) c0 = e0b[m];
        if (MODE == 2) { c0 = e0b[m]; c1 = e2b[m]; }
        float r[TN];
        #pragma unroll
        for (int j = 0; j < TN; j++) {
            r[j] = acc[i][j];
            if (MODE == 1) r[j] += c0;
            if (MODE == 2) r[j] += c0 * e1b[n0 + j] + c1 * e3b[n0 + j];
        }
        float4* dst = reinterpret_cast<float4*>(Cb + (size_t)m * ldc + n0);
        dst[0] = make_float4(r[0], r[1], r[2], r[3]);
        dst[1] = make_float4(r[4], r[5], r[6], r[7]);
    }
}

// ---------------------------------------------------------------------------
// s[bat][c] = sum_n X[bat,c,n]
// ---------------------------------------------------------------------------
__global__ __launch_bounds__(256)
void rowsum_kernel(const float* __restrict__ X, float* __restrict__ s)
{
    const int bat = blockIdx.y, row = blockIdx.x;
    const float* xr = X + ((size_t)bat * 512 + row) * 4096;
    float acc = 0.f;
    for (int i = threadIdx.x; i < 4096; i += 256) acc += xr[i];
    __shared__ float sh[8];
    #pragma unroll
    for (int o = 16; o; o >>= 1) acc += __shfl_xor_sync(0xffffffffu, acc, o);
    if ((threadIdx.x & 31) == 0) sh[threadIdx.x >> 5] = acc;
    __syncthreads();
    if (threadIdx.x < 32) {
        float t = (threadIdx.x < 8) ? sh[threadIdx.x] : 0.f;
        #pragma unroll
        for (int o = 4; o; o >>= 1) t += __shfl_xor_sync(0xffffffffu, t, o);
        if (threadIdx.x == 0) s[(size_t)bat * 512 + row] = t;
    }
}

// ---------------------------------------------------------------------------
// y[bat][m] = W[m,:] . s[bat,:]  (+ bscale * bias[m]).  One warp per row.
// ---------------------------------------------------------------------------
__global__ __launch_bounds__(256)
void gemv_kernel(const float* __restrict__ W, const float* __restrict__ s,
                 const float* __restrict__ bias, float bscale,
                 float* __restrict__ y, int Mrows, int Kc)
{
    const int bat  = blockIdx.y;
    const int warp = threadIdx.x >> 5, lane = threadIdx.x & 31;
    const int row  = blockIdx.x * 8 + warp;
    const float* sv = s + (size_t)bat * Kc;
    const float* w  = W + (size_t)row * Kc;
    float acc = 0.f;
    for (int c = lane; c < Kc; c += 32) acc += w[c] * sv[c];
    #pragma unroll
    for (int o = 16; o; o >>= 1) acc += __shfl_xor_sync(0xffffffffu, acc, o);
    if (lane == 0) {
        float b = bias ? bscale * bias[row] : 0.f;
        y[(size_t)bat * Mrows + row] = acc + b;
    }
}

// ---------------------------------------------------------------------------
// G[bat] = sum over 8 split-K partials
// ---------------------------------------------------------------------------
__global__ __launch_bounds__(256)
void greduce_kernel(const float* __restrict__ Gp, float* __restrict__ G)
{
    const int bat = blockIdx.y;
    const int i = blockIdx.x * 256 + threadIdx.x;     // < 262144
    const float* p = Gp + (size_t)bat * 8 * 262144 + i;
    float acc = 0.f;
    #pragma unroll
    for (int sp = 0; sp < 8; sp++) acc += p[(size_t)sp * 262144];
    G[(size_t)bat * 262144 + i] = acc;
}

// ---------------------------------------------------------------------------
// In-place row softmax: rows of length 4096. grid(4096, batch).
// ---------------------------------------------------------------------------
__global__ __launch_bounds__(256)
void softmax_kernel(float* __restrict__ E)
{
    float* row = E + ((size_t)blockIdx.y * 4096 + blockIdx.x) * 4096;
    const int tid = threadIdx.x;
    float vals[16];
    float m = -1e30f;
    #pragma unroll
    for (int i = 0; i < 16; i++) {
        vals[i] = row[tid + i * 256];
        m = fmaxf(m, vals[i]);
    }
    __shared__ float sh[8];
    #pragma unroll
    for (int o = 16; o; o >>= 1) m = fmaxf(m, __shfl_xor_sync(0xffffffffu, m, o));
    if ((tid & 31) == 0) sh[tid >> 5] = m;
    __syncthreads();
    if (tid < 32) {
        float t = (tid < 8) ? sh[tid] : -1e30f;
        #pragma unroll
        for (int o = 4; o; o >>= 1) t = fmaxf(t, __shfl_xor_sync(0xffffffffu, t, o));
        if (tid == 0) sh[0] = t;
    }
    __syncthreads();
    m = sh[0];
    __syncthreads();                      // sh reused below
    float s = 0.f;
    #pragma unroll
    for (int i = 0; i < 16; i++) {
        vals[i] = __expf(vals[i] - m);
        s += vals[i];
    }
    #pragma unroll
    for (int o = 16; o; o >>= 1) s += __shfl_xor_sync(0xffffffffu, s, o);
    if ((tid & 31) == 0) sh[tid >> 5] = s;
    __syncthreads();
    if (tid < 32) {
        float t = (tid < 8) ? sh[tid] : 0.f;
        #pragma unroll
        for (int o = 4; o; o >>= 1) t += __shfl_xor_sync(0xffffffffu, t, o);
        if (tid == 0) sh[0] = t;
    }
    __syncthreads();
    const float inv = 1.0f / sh[0];
    #pragma unroll
    for (int i = 0; i < 16; i++)
        row[tid + i * 256] = vals[i] * inv;
}

// ---------------------------------------------------------------------------
extern "C" void kernel_launch(void* const* d_in, const int* in_sizes, int n_in,
                              void* d_out, int out_size)
{
    const float* x  = (const float*)d_in[0];   // [4,512,64,64] -> [4,512,4096]
    const float* Wq = (const float*)d_in[1];   // [4096,512]
    const float* bq = (const float*)d_in[2];   // [4096]
    const float* Wk = (const float*)d_in[3];   // [4096,512]
    const float* bk = (const float*)d_in[4];   // [4096]
    const float* Wv = (const float*)d_in[5];   // [512,512]
    const float* bv = (const float*)d_in[6];   // [512]
    float* out = (float*)d_out;                // [4,512,4096]

    float *s, *u1, *u2, *Gp, *G, *Khat, *V, *E;
    cudaGetSymbolAddress((void**)&s,    g_s);
    cudaGetSymbolAddress((void**)&u1,   g_u1);
    cudaGetSymbolAddress((void**)&u2,   g_u2);
    cudaGetSymbolAddress((void**)&Gp,   g_Gp);
    cudaGetSymbolAddress((void**)&G,    g_G);
    cudaGetSymbolAddress((void**)&Khat, g_Khat);
    cudaGetSymbolAddress((void**)&V,    g_v);
    cudaGetSymbolAddress((void**)&E,    g_E);

    const long long sX  = 512LL * 4096;       // batch stride of X / V
    const long long sE  = 4096LL * 4096;      // batch stride of E
    const long long sKh = 4096LL * 512;       // batch stride of Khat

    dim3 blk(NTHREADS);

    // s[b] = X_b . 1
    rowsum_kernel<<<dim3(512, 4), 256>>>(x, s);
    // u1 = Wq s + 4096*bq ; u2 = Wk s
    gemv_kernel<<<dim3(512, 4), 256>>>(Wq, s, bq, 4096.0f, u1, 4096, 512);
    gemv_kernel<<<dim3(512, 4), 256>>>(Wk, s, nullptr, 0.0f, u2, 4096, 512);

    // G_b = X_b X_bᵀ  (split-K over n: 8 splits of 512)
    sgemm_kernel<0, true><<<dim3(4, 4, 32), blk>>>(
        x, x, Gp, 512, 512, 512, 4096, 4096, 512,
        sX, sX, 8LL * 262144, /*nsplit=*/8, 512, 512, 262144,
        nullptr, 0, nullptr, 0, nullptr, 0, nullptr, 0);
    greduce_kernel<<<dim3(1024, 4), 256>>>(Gp, G);

    // Khat_b = Wk G_b   [4096, 512]
    sgemm_kernel<0, false><<<dim3(4, 32, 4), blk>>>(
        Wk, G, Khat, 4096, 512, 512, 512, 512, 512,
        0, 262144, sKh, 1, 0, 0, 0,
        nullptr, 0, nullptr, 0, nullptr, 0, nullptr, 0);

    // V_b = Wv X_b + bv   [512, 4096]
    sgemm_kernel<1, false><<<dim3(32, 4, 4), blk>>>(
        Wv, x, V, 512, 4096, 512, 512, 4096, 4096,
        0, sX, sX, 1, 0, 0, 0,
        bv, 0, nullptr, 0, nullptr, 0, nullptr, 0);

    // E_b = Wq Khat_bᵀ + u1 bkᵀ + bq u2ᵀ   [4096, 4096]
    sgemm_kernel<2, true><<<dim3(32, 32, 4), blk>>>(
        Wq, Khat, E, 4096, 4096, 512, 512, 512, 4096,
        0, sKh, sE, 1, 0, 0, 0,
        u1, 4096, bk, 0, bq, 0, u2, 4096);

    // P_b = softmax rows of E_b (in place)
    softmax_kernel<<<dim3(4096, 4), 256>>>(E);

    // out_b = V_b P_bᵀ   [512, 4096]
    sgemm_kernel<0, true><<<dim3(32, 4, 4), blk>>>(
        V, E, out, 512, 4096, 4096, 4096, 4096, 4096,
        sX, sE, sX, 1, 0, 0, 0,
        nullptr, 0, nullptr, 0, nullptr, 0, nullptr, 0);
}